// round 1
// baseline (speedup 1.0000x reference)
#include <cuda_runtime.h>

#define BTOT   131072
#define DID    64
#define ROWS   32
#define NT     128
#define KT     16
#define HID    256
#define PTOT   736

typedef unsigned long long u64;

__device__ __forceinline__ u64 fma2v(u64 a, u64 b, u64 c) {
    u64 d; asm("fma.rn.f32x2 %0, %1, %2, %3;" : "=l"(d) : "l"(a), "l"(b), "l"(c)); return d;
}
__device__ __forceinline__ u64 dup2(float x) {
    u64 d; unsigned u = __float_as_uint(x);
    asm("mov.b64 %0, {%1, %1};" : "=l"(d) : "r"(u)); return d;
}
__device__ __forceinline__ float2 unpk(u64 v) {
    float2 f; asm("mov.b64 {%0, %1}, %2;" : "=f"(f.x), "=f"(f.y) : "l"(v)); return f;
}

// shared memory layout (float offsets)
#define OFF_IN    0        // 32*64   = 2048 floats (input tile; y written back in-place)
#define OFF_IDT   2048     // 32*36   = 1152 floats (identity half, [k][r], stride 36)
#define OFF_HBUF  3200     // 256*36  = 9216 floats (h activations, [k][r])
#define OFF_TBUF  12416    // 256*36  = 9216 floats (t activations, [k][r])
#define OFF_WT    21632    // 16*256 u64 = 8192 floats (weight k-tile, value-duplicated)
#define OFF_PS    29824    // 32*768  = 24576 floats (spline params per row)
#define SMEM_FLOATS 54400  // 217600 bytes

// GEMM: acc[rowpair] over 32 rows for 2 columns (c0=tid, c1=tid+128), K-tiled.
// act is SMEM [K][36] (k-major, rows contiguous). W is global [wrows][K] row-major.
__device__ __forceinline__ void gemm2(
    const float* __restrict__ W, int wrows, int colbase, int K,
    const float* __restrict__ act, u64* wtd,
    u64* acc0, u64* acc1, int tid)
{
    for (int k0 = 0; k0 < K; k0 += KT) {
        __syncthreads();
        // stage KT x 256 weight tile, duplicated into both f32x2 lanes
        #pragma unroll
        for (int j = 0; j < 8; j++) {
            int lin = tid + NT * j;        // 0..1023
            int c = lin >> 2, q = lin & 3;
            int grow = colbase + c;
            float4 f = make_float4(0.f, 0.f, 0.f, 0.f);
            if (grow < wrows)
                f = __ldg(((const float4*)(W + (size_t)grow * K + k0)) + q);
            wtd[(q * 4 + 0) * 256 + c] = dup2(f.x);
            wtd[(q * 4 + 1) * 256 + c] = dup2(f.y);
            wtd[(q * 4 + 2) * 256 + c] = dup2(f.z);
            wtd[(q * 4 + 3) * 256 + c] = dup2(f.w);
        }
        __syncthreads();
        #pragma unroll 4
        for (int kk = 0; kk < KT; kk++) {
            u64 w0 = wtd[kk * 256 + tid];
            u64 w1 = wtd[kk * 256 + tid + 128];
            const ulonglong2* hrow = (const ulonglong2*)(act + (k0 + kk) * 36);
            #pragma unroll
            for (int q = 0; q < 8; q++) {
                ulonglong2 hv = hrow[q];           // rows 4q..4q+3 at this k
                acc0[2 * q]     = fma2v(hv.x, w0, acc0[2 * q]);
                acc0[2 * q + 1] = fma2v(hv.y, w0, acc0[2 * q + 1]);
                acc1[2 * q]     = fma2v(hv.x, w1, acc1[2 * q]);
                acc1[2 * q + 1] = fma2v(hv.y, w1, acc1[2 * q + 1]);
            }
        }
    }
}

__device__ __forceinline__ void mk_knots(const float* pp, float* kn) {
    float e[8];
    float mx = -1e30f;
    #pragma unroll
    for (int j = 0; j < 8; j++) { e[j] = pp[j] * 0.0625f; mx = fmaxf(mx, e[j]); }
    float se = 0.f;
    #pragma unroll
    for (int j = 0; j < 8; j++) { e[j] = expf(e[j] - mx); se += e[j]; }
    float inv = 1.f / se, cum = 0.f;
    kn[0] = -3.f;
    #pragma unroll
    for (int j = 0; j < 8; j++) {
        cum += 0.001f + 0.992f * e[j] * inv;
        kn[j + 1] = 6.f * cum - 3.f;
    }
    kn[8] = 3.f;
}

__global__ void __launch_bounds__(NT, 1)
coupling_kernel(const float* __restrict__ inp,
                const float* __restrict__ w_in, const float* __restrict__ b_in,
                const float* __restrict__ w0a,  const float* __restrict__ b0a,
                const float* __restrict__ w1a,  const float* __restrict__ b1a,
                const float* __restrict__ w0b,  const float* __restrict__ b0b,
                const float* __restrict__ w1b,  const float* __restrict__ b1b,
                const float* __restrict__ w_out, const float* __restrict__ b_out,
                float* __restrict__ out)
{
    extern __shared__ float sm[];
    const int tid = threadIdx.x;
    const int row0 = blockIdx.x * ROWS;

    float* smin = sm + OFF_IN;
    float* idt  = sm + OFF_IDT;
    float* hbuf = sm + OFF_HBUF;
    float* tbuf = sm + OFF_TBUF;
    u64*   wtd  = (u64*)(sm + OFF_WT);
    float* ps   = sm + OFF_PS;

    // ---- load input tile (32 x 64) ----
    {
        const float4* g  = (const float4*)(inp + (size_t)row0 * DID);
        float4*       s4 = (float4*)smin;
        #pragma unroll
        for (int j = 0; j < 4; j++) s4[tid + NT * j] = g[tid + NT * j];
    }
    __syncthreads();
    // ---- identity half, transposed [k][r] ----
    #pragma unroll
    for (int j = 0; j < 8; j++) {
        int i = tid + NT * j;           // 0..1023
        int k = i >> 5, r = i & 31;
        idt[k * 36 + r] = smin[r * 64 + 2 * k + 1];
    }

    u64 acc0[16], acc1[16];
    float2 hA[16], hB[16];
    const int c0 = tid, c1 = tid + 128;

    // ---- h = ident @ w_in^T + b_in ----
    #pragma unroll
    for (int q = 0; q < 16; q++) { acc0[q] = 0ull; acc1[q] = 0ull; }
    gemm2(w_in, 256, 0, 32, idt, wtd, acc0, acc1, tid);
    {
        float bb0 = __ldg(b_in + c0), bb1 = __ldg(b_in + c1);
        float2* h0p = (float2*)(hbuf + c0 * 36);
        float2* h1p = (float2*)(hbuf + c1 * 36);
        #pragma unroll
        for (int q = 0; q < 16; q++) {
            float2 t0 = unpk(acc0[q]);
            hA[q] = make_float2(t0.x + bb0, t0.y + bb0);
            float2 t1 = unpk(acc1[q]);
            hB[q] = make_float2(t1.x + bb1, t1.y + bb1);
            h0p[q] = make_float2(fmaxf(hA[q].x, 0.f), fmaxf(hA[q].y, 0.f));
            h1p[q] = make_float2(fmaxf(hB[q].x, 0.f), fmaxf(hB[q].y, 0.f));
        }
    }

    // ---- two residual blocks ----
    const float* W0s[2] = { w0a, w0b };
    const float* B0s[2] = { b0a, b0b };
    const float* W1s[2] = { w1a, w1b };
    const float* B1s[2] = { b1a, b1b };
    #pragma unroll 1
    for (int blk = 0; blk < 2; blk++) {
        // t1 = relu(h) @ w0^T + b0   (hbuf currently holds relu(h))
        #pragma unroll
        for (int q = 0; q < 16; q++) { acc0[q] = 0ull; acc1[q] = 0ull; }
        gemm2(W0s[blk], 256, 0, 256, hbuf, wtd, acc0, acc1, tid);
        {
            float bb0 = __ldg(B0s[blk] + c0), bb1 = __ldg(B0s[blk] + c1);
            float2* t0p = (float2*)(tbuf + c0 * 36);
            float2* t1p = (float2*)(tbuf + c1 * 36);
            #pragma unroll
            for (int q = 0; q < 16; q++) {
                float2 t0 = unpk(acc0[q]);
                t0p[q] = make_float2(fmaxf(t0.x + bb0, 0.f), fmaxf(t0.y + bb0, 0.f));
                float2 t1 = unpk(acc1[q]);
                t1p[q] = make_float2(fmaxf(t1.x + bb1, 0.f), fmaxf(t1.y + bb1, 0.f));
            }
        }
        // t2 = relu(t1) @ w1^T + b1 ; h += t2 ; store relu(h)
        #pragma unroll
        for (int q = 0; q < 16; q++) { acc0[q] = 0ull; acc1[q] = 0ull; }
        gemm2(W1s[blk], 256, 0, 256, tbuf, wtd, acc0, acc1, tid);
        {
            float bb0 = __ldg(B1s[blk] + c0), bb1 = __ldg(B1s[blk] + c1);
            float2* h0p = (float2*)(hbuf + c0 * 36);
            float2* h1p = (float2*)(hbuf + c1 * 36);
            #pragma unroll
            for (int q = 0; q < 16; q++) {
                float2 t0 = unpk(acc0[q]);
                hA[q].x += t0.x + bb0; hA[q].y += t0.y + bb0;
                float2 t1 = unpk(acc1[q]);
                hB[q].x += t1.x + bb1; hB[q].y += t1.y + bb1;
                h0p[q] = make_float2(fmaxf(hA[q].x, 0.f), fmaxf(hA[q].y, 0.f));
                h1p[q] = make_float2(fmaxf(hB[q].x, 0.f), fmaxf(hB[q].y, 0.f));
            }
        }
    }
    // ---- overwrite hbuf with raw (pre-relu) h for the output GEMM ----
    {
        float2* h0p = (float2*)(hbuf + c0 * 36);
        float2* h1p = (float2*)(hbuf + c1 * 36);
        #pragma unroll
        for (int q = 0; q < 16; q++) { h0p[q] = hA[q]; h1p[q] = hB[q]; }
    }

    // ---- params = h @ w_out^T + b_out  (736 cols in 3 chunks of 256) ----
    #pragma unroll 1
    for (int jj = 0; jj < 3; jj++) {
        #pragma unroll
        for (int q = 0; q < 16; q++) { acc0[q] = 0ull; acc1[q] = 0ull; }
        gemm2(w_out, PTOT, jj * 256, 256, hbuf, wtd, acc0, acc1, tid);
        int p0 = jj * 256 + tid, p1 = p0 + 128;
        float bo0 = __ldg(b_out + p0);                         // p0 <= 639 < 736
        float bo1 = (p1 < PTOT) ? __ldg(b_out + p1) : 0.f;
        #pragma unroll
        for (int q = 0; q < 16; q++) {
            float2 t0 = unpk(acc0[q]);
            ps[(2 * q)     * 768 + p0] = t0.x + bo0;
            ps[(2 * q + 1) * 768 + p0] = t0.y + bo0;
            float2 t1 = unpk(acc1[q]);
            ps[(2 * q)     * 768 + p1] = t1.x + bo1;          // pad region if p1>=736
            ps[(2 * q + 1) * 768 + p1] = t1.y + bo1;
        }
    }
    __syncthreads();

    // ---- RQ spline: 32 rows x 32 dims; 4 threads per row, 8 dims each ----
    {
        int r  = tid >> 2;
        int dl = tid & 3;
        float ladacc = 0.f;
        #pragma unroll 1
        for (int i = 0; i < 8; i++) {
            int d = dl + 4 * i;
            const float* pp = ps + r * 768 + d * 23;
            float knw[9], knh[9], dv[9];
            mk_knots(pp,     knw);
            mk_knots(pp + 8, knh);
            dv[0] = 1.f; dv[8] = 1.f;
            #pragma unroll
            for (int j = 1; j < 8; j++) {
                float t = pp[15 + j];   // ud[j-1]
                dv[j] = 0.001f + fmaxf(t, 0.f) + log1pf(expf(-fabsf(t)));
            }
            float x  = smin[r * 64 + 2 * d];
            float xc = fminf(fmaxf(x, -3.f), 3.f);
            int idx = -1;
            #pragma unroll
            for (int j = 0; j < 9; j++) idx += (xc >= knw[j]) ? 1 : 0;
            idx = min(max(idx, 0), 7);
            float kw0 = knw[idx], kw1 = knw[idx + 1];
            float kh0 = knh[idx], kh1 = knh[idx + 1];
            float wdt = kw1 - kw0, hgt = kh1 - kh0;
            float delta = hgt / wdt;
            float d0v = dv[idx], d1v = dv[idx + 1];
            float th  = (xc - kw0) / wdt;
            float tom = th * (1.f - th);
            float num = hgt * (delta * th * th + d0v * tom);
            float den = delta + (d0v + d1v - 2.f * delta) * tom;
            float y   = kh0 + num / den;
            float omt = 1.f - th;
            float dnum = delta * delta * (d1v * th * th + 2.f * delta * tom + d0v * omt * omt);
            float lad  = logf(dnum) - 2.f * logf(den);
            bool inside = (x >= -3.f) && (x <= 3.f);
            if (!inside) { y = x; lad = 0.f; }
            smin[r * 64 + 2 * d] = y;
            ladacc += lad;
        }
        ladacc += __shfl_xor_sync(0xffffffffu, ladacc, 1);
        ladacc += __shfl_xor_sync(0xffffffffu, ladacc, 2);
        if (dl == 0) out[(size_t)BTOT * DID + row0 + r] = ladacc;
    }
    __syncthreads();

    // ---- coalesced writeback of the assembled output tile ----
    {
        float4*       o4 = (float4*)(out + (size_t)row0 * DID);
        const float4* s4 = (const float4*)smin;
        #pragma unroll
        for (int j = 0; j < 4; j++) o4[tid + NT * j] = s4[tid + NT * j];
    }
}

extern "C" void kernel_launch(void* const* d_in, const int* in_sizes, int n_in,
                              void* d_out, int out_size)
{
    cudaFuncSetAttribute(coupling_kernel,
                         cudaFuncAttributeMaxDynamicSharedMemorySize,
                         SMEM_FLOATS * 4);
    const float* inp   = (const float*)d_in[0];
    const float* w_in  = (const float*)d_in[1];
    const float* b_in  = (const float*)d_in[2];
    const float* w0a   = (const float*)d_in[3];
    const float* b0a   = (const float*)d_in[4];
    const float* w1a   = (const float*)d_in[5];
    const float* b1a   = (const float*)d_in[6];
    const float* w0b   = (const float*)d_in[7];
    const float* b0b   = (const float*)d_in[8];
    const float* w1b   = (const float*)d_in[9];
    const float* b1b   = (const float*)d_in[10];
    const float* w_out = (const float*)d_in[11];
    const float* b_out = (const float*)d_in[12];
    float* out = (float*)d_out;

    coupling_kernel<<<BTOT / ROWS, NT, SMEM_FLOATS * 4>>>(
        inp, w_in, b_in, w0a, b0a, w1a, b1a, w0b, b0b, w1b, b1b, w_out, b_out, out);
}

// round 3
// speedup vs baseline: 1.0492x; 1.0492x over previous
#include <cuda_runtime.h>

#define BTOT   131072
#define DID    64
#define ROWS   32
#define NT     128
#define KT     8
#define HID    256
#define PTOT   736

typedef unsigned long long u64;

__device__ __forceinline__ u64 fma2v(u64 a, u64 b, u64 c) {
    u64 d; asm("fma.rn.f32x2 %0, %1, %2, %3;" : "=l"(d) : "l"(a), "l"(b), "l"(c)); return d;
}
__device__ __forceinline__ u64 dup2(float x) {
    u64 d; unsigned u = __float_as_uint(x);
    asm("mov.b64 %0, {%1, %1};" : "=l"(d) : "r"(u)); return d;
}
__device__ __forceinline__ float2 unpk(u64 v) {
    float2 f; asm("mov.b64 {%0, %1}, %2;" : "=f"(f.x), "=f"(f.y) : "l"(v)); return f;
}

// shared memory layout (float offsets)
#define OFF_IN    0        // 32*64   = 2048 floats (input tile; y written back in-place)
#define OFF_IDT   2048     // 32*36   = 1152 floats (identity half, [k][r], stride 36)
#define OFF_HBUF  3200     // 256*36  = 9216 floats (h activations, [k][r])
#define OFF_TBUF  12416    // 256*36  = 9216 floats (t activations, [k][r])
#define OFF_WT    21632    // 8*256 u64 = 4096 floats (single weight k-tile, value-duplicated)
#define OFF_PS    25728    // 32*768  = 24576 floats (spline params per row)
#define SMEM_FLOATS 50304  // 201216 bytes

// GEMM: acc[rowpair] over 32 rows for 2 columns (c0=tid, c1=tid+128), K-tiled (KT=8),
// with the NEXT weight tile prefetched into registers while the current tile computes.
// act is SMEM [K][36] (k-major, rows contiguous). W is global [wrows][K] row-major.
__device__ __forceinline__ void gemm2(
    const float* __restrict__ W, int wrows, int colbase, int K,
    const float* __restrict__ act, u64* wtd,
    u64* acc0, u64* acc1, int tid)
{
    const int nt = K >> 3;
    float4 pf[4];
    // prologue: prefetch tile 0 into registers (lin = tid + 128*j, c = lin>>1, q = lin&1)
    #pragma unroll
    for (int j = 0; j < 4; j++) {
        int lin = tid + NT * j;
        int c = lin >> 1, q = lin & 1;
        int grow = colbase + c;
        pf[j] = (grow < wrows)
              ? __ldg(((const float4*)(W + (size_t)grow * K)) + q)
              : make_float4(0.f, 0.f, 0.f, 0.f);
    }

    for (int t = 0; t < nt; t++) {
        __syncthreads();   // all consumers done with previous tile / previous GEMM's wtd
        // store prefetched tile t into smem, value-duplicated for f32x2
        #pragma unroll
        for (int j = 0; j < 4; j++) {
            int lin = tid + NT * j;
            int c = lin >> 1, q = lin & 1;
            wtd[(4 * q + 0) * 256 + c] = dup2(pf[j].x);
            wtd[(4 * q + 1) * 256 + c] = dup2(pf[j].y);
            wtd[(4 * q + 2) * 256 + c] = dup2(pf[j].z);
            wtd[(4 * q + 3) * 256 + c] = dup2(pf[j].w);
        }
        // prefetch tile t+1 (latency hidden under compute of tile t)
        if (t + 1 < nt) {
            int k0 = (t + 1) << 3;
            #pragma unroll
            for (int j = 0; j < 4; j++) {
                int lin = tid + NT * j;
                int c = lin >> 1, q = lin & 1;
                int grow = colbase + c;
                pf[j] = (grow < wrows)
                      ? __ldg(((const float4*)(W + (size_t)grow * K + k0)) + q)
                      : make_float4(0.f, 0.f, 0.f, 0.f);
            }
        }
        __syncthreads();   // tile t visible to all
        #pragma unroll 2
        for (int kk = 0; kk < 8; kk++) {
            u64 w0 = wtd[kk * 256 + tid];
            u64 w1 = wtd[kk * 256 + tid + 128];
            const ulonglong2* hrow = (const ulonglong2*)(act + ((t << 3) + kk) * 36);
            #pragma unroll
            for (int q = 0; q < 8; q++) {
                ulonglong2 hv = hrow[q];           // rows 4q..4q+3 at this k
                acc0[2 * q]     = fma2v(hv.x, w0, acc0[2 * q]);
                acc0[2 * q + 1] = fma2v(hv.y, w0, acc0[2 * q + 1]);
                acc1[2 * q]     = fma2v(hv.x, w1, acc1[2 * q]);
                acc1[2 * q + 1] = fma2v(hv.y, w1, acc1[2 * q + 1]);
            }
        }
    }
}

__device__ __forceinline__ void mk_knots(const float* pp, float* kn) {
    float e[8];
    float mx = -1e30f;
    #pragma unroll
    for (int j = 0; j < 8; j++) { e[j] = pp[j] * 0.0625f; mx = fmaxf(mx, e[j]); }
    float se = 0.f;
    #pragma unroll
    for (int j = 0; j < 8; j++) { e[j] = expf(e[j] - mx); se += e[j]; }
    float inv = 1.f / se, cum = 0.f;
    kn[0] = -3.f;
    #pragma unroll
    for (int j = 0; j < 8; j++) {
        cum += 0.001f + 0.992f * e[j] * inv;
        kn[j + 1] = 6.f * cum - 3.f;
    }
    kn[8] = 3.f;
}

__global__ void __launch_bounds__(NT, 1)
coupling_kernel(const float* __restrict__ inp,
                const float* __restrict__ w_in, const float* __restrict__ b_in,
                const float* __restrict__ w0a,  const float* __restrict__ b0a,
                const float* __restrict__ w1a,  const float* __restrict__ b1a,
                const float* __restrict__ w0b,  const float* __restrict__ b0b,
                const float* __restrict__ w1b,  const float* __restrict__ b1b,
                const float* __restrict__ w_out, const float* __restrict__ b_out,
                float* __restrict__ out)
{
    extern __shared__ float sm[];
    const int tid = threadIdx.x;
    const int row0 = blockIdx.x * ROWS;

    float* smin = sm + OFF_IN;
    float* idt  = sm + OFF_IDT;
    float* hbuf = sm + OFF_HBUF;
    float* tbuf = sm + OFF_TBUF;
    u64*   wtd  = (u64*)(sm + OFF_WT);
    float* ps   = sm + OFF_PS;

    // ---- load input tile (32 x 64) ----
    {
        const float4* g  = (const float4*)(inp + (size_t)row0 * DID);
        float4*       s4 = (float4*)smin;
        #pragma unroll
        for (int j = 0; j < 4; j++) s4[tid + NT * j] = g[tid + NT * j];
    }
    __syncthreads();
    // ---- identity half, transposed [k][r] ----
    #pragma unroll
    for (int j = 0; j < 8; j++) {
        int i = tid + NT * j;           // 0..1023
        int k = i >> 5, r = i & 31;
        idt[k * 36 + r] = smin[r * 64 + 2 * k + 1];
    }

    u64 acc0[16], acc1[16];
    float2 hA[16], hB[16];
    const int c0 = tid, c1 = tid + 128;

    // ---- h = ident @ w_in^T + b_in ----
    #pragma unroll
    for (int q = 0; q < 16; q++) { acc0[q] = 0ull; acc1[q] = 0ull; }
    gemm2(w_in, 256, 0, 32, idt, wtd, acc0, acc1, tid);
    {
        float bb0 = __ldg(b_in + c0), bb1 = __ldg(b_in + c1);
        float2* h0p = (float2*)(hbuf + c0 * 36);
        float2* h1p = (float2*)(hbuf + c1 * 36);
        #pragma unroll
        for (int q = 0; q < 16; q++) {
            float2 t0 = unpk(acc0[q]);
            hA[q] = make_float2(t0.x + bb0, t0.y + bb0);
            float2 t1 = unpk(acc1[q]);
            hB[q] = make_float2(t1.x + bb1, t1.y + bb1);
            h0p[q] = make_float2(fmaxf(hA[q].x, 0.f), fmaxf(hA[q].y, 0.f));
            h1p[q] = make_float2(fmaxf(hB[q].x, 0.f), fmaxf(hB[q].y, 0.f));
        }
    }

    // ---- two residual blocks ----
    const float* W0s[2] = { w0a, w0b };
    const float* B0s[2] = { b0a, b0b };
    const float* W1s[2] = { w1a, w1b };
    const float* B1s[2] = { b1a, b1b };
    #pragma unroll 1
    for (int blk = 0; blk < 2; blk++) {
        // t1 = relu(h) @ w0^T + b0   (hbuf currently holds relu(h))
        #pragma unroll
        for (int q = 0; q < 16; q++) { acc0[q] = 0ull; acc1[q] = 0ull; }
        gemm2(W0s[blk], 256, 0, 256, hbuf, wtd, acc0, acc1, tid);
        {
            float bb0 = __ldg(B0s[blk] + c0), bb1 = __ldg(B0s[blk] + c1);
            float2* t0p = (float2*)(tbuf + c0 * 36);
            float2* t1p = (float2*)(tbuf + c1 * 36);
            #pragma unroll
            for (int q = 0; q < 16; q++) {
                float2 t0 = unpk(acc0[q]);
                t0p[q] = make_float2(fmaxf(t0.x + bb0, 0.f), fmaxf(t0.y + bb0, 0.f));
                float2 t1 = unpk(acc1[q]);
                t1p[q] = make_float2(fmaxf(t1.x + bb1, 0.f), fmaxf(t1.y + bb1, 0.f));
            }
        }
        // t2 = relu(t1) @ w1^T + b1 ; h += t2 ; store relu(h)
        #pragma unroll
        for (int q = 0; q < 16; q++) { acc0[q] = 0ull; acc1[q] = 0ull; }
        gemm2(W1s[blk], 256, 0, 256, tbuf, wtd, acc0, acc1, tid);
        {
            float bb0 = __ldg(B1s[blk] + c0), bb1 = __ldg(B1s[blk] + c1);
            float2* h0p = (float2*)(hbuf + c0 * 36);
            float2* h1p = (float2*)(hbuf + c1 * 36);
            #pragma unroll
            for (int q = 0; q < 16; q++) {
                float2 t0 = unpk(acc0[q]);
                hA[q].x += t0.x + bb0; hA[q].y += t0.y + bb0;
                float2 t1 = unpk(acc1[q]);
                hB[q].x += t1.x + bb1; hB[q].y += t1.y + bb1;
                h0p[q] = make_float2(fmaxf(hA[q].x, 0.f), fmaxf(hA[q].y, 0.f));
                h1p[q] = make_float2(fmaxf(hB[q].x, 0.f), fmaxf(hB[q].y, 0.f));
            }
        }
    }
    // ---- overwrite hbuf with raw (pre-relu) h for the output GEMM ----
    {
        float2* h0p = (float2*)(hbuf + c0 * 36);
        float2* h1p = (float2*)(hbuf + c1 * 36);
        #pragma unroll
        for (int q = 0; q < 16; q++) { h0p[q] = hA[q]; h1p[q] = hB[q]; }
    }

    // ---- params = h @ w_out^T + b_out  (736 cols in 3 chunks of 256) ----
    #pragma unroll 1
    for (int jj = 0; jj < 3; jj++) {
        #pragma unroll
        for (int q = 0; q < 16; q++) { acc0[q] = 0ull; acc1[q] = 0ull; }
        gemm2(w_out, PTOT, jj * 256, 256, hbuf, wtd, acc0, acc1, tid);
        int p0 = jj * 256 + tid, p1 = p0 + 128;
        float bo0 = __ldg(b_out + p0);                         // p0 <= 639 < 736
        float bo1 = (p1 < PTOT) ? __ldg(b_out + p1) : 0.f;
        #pragma unroll
        for (int q = 0; q < 16; q++) {
            float2 t0 = unpk(acc0[q]);
            ps[(2 * q)     * 768 + p0] = t0.x + bo0;
            ps[(2 * q + 1) * 768 + p0] = t0.y + bo0;
            float2 t1 = unpk(acc1[q]);
            ps[(2 * q)     * 768 + p1] = t1.x + bo1;          // pad region if p1>=736
            ps[(2 * q + 1) * 768 + p1] = t1.y + bo1;
        }
    }
    __syncthreads();

    // ---- RQ spline: 32 rows x 32 dims; 4 threads per row, 8 dims each ----
    {
        int r  = tid >> 2;
        int dl = tid & 3;
        float ladacc = 0.f;
        #pragma unroll 1
        for (int i = 0; i < 8; i++) {
            int d = dl + 4 * i;
            const float* pp = ps + r * 768 + d * 23;
            float knw[9], knh[9], dv[9];
            mk_knots(pp,     knw);
            mk_knots(pp + 8, knh);
            dv[0] = 1.f; dv[8] = 1.f;
            #pragma unroll
            for (int j = 1; j < 8; j++) {
                float t = pp[15 + j];   // ud[j-1]
                dv[j] = 0.001f + fmaxf(t, 0.f) + log1pf(expf(-fabsf(t)));
            }
            float x  = smin[r * 64 + 2 * d];
            float xc = fminf(fmaxf(x, -3.f), 3.f);
            int idx = -1;
            #pragma unroll
            for (int j = 0; j < 9; j++) idx += (xc >= knw[j]) ? 1 : 0;
            idx = min(max(idx, 0), 7);
            float kw0 = knw[idx], kw1 = knw[idx + 1];
            float kh0 = knh[idx], kh1 = knh[idx + 1];
            float wdt = kw1 - kw0, hgt = kh1 - kh0;
            float delta = hgt / wdt;
            float d0v = dv[idx], d1v = dv[idx + 1];
            float th  = (xc - kw0) / wdt;
            float tom = th * (1.f - th);
            float num = hgt * (delta * th * th + d0v * tom);
            float den = delta + (d0v + d1v - 2.f * delta) * tom;
            float y   = kh0 + num / den;
            float omt = 1.f - th;
            float dnum = delta * delta * (d1v * th * th + 2.f * delta * tom + d0v * omt * omt);
            float lad  = logf(dnum) - 2.f * logf(den);
            bool inside = (x >= -3.f) && (x <= 3.f);
            if (!inside) { y = x; lad = 0.f; }
            smin[r * 64 + 2 * d] = y;
            ladacc += lad;
        }
        ladacc += __shfl_xor_sync(0xffffffffu, ladacc, 1);
        ladacc += __shfl_xor_sync(0xffffffffu, ladacc, 2);
        if (dl == 0) out[(size_t)BTOT * DID + row0 + r] = ladacc;
    }
    __syncthreads();

    // ---- coalesced writeback of the assembled output tile ----
    {
        float4*       o4 = (float4*)(out + (size_t)row0 * DID);
        const float4* s4 = (const float4*)smin;
        #pragma unroll
        for (int j = 0; j < 4; j++) o4[tid + NT * j] = s4[tid + NT * j];
    }
}

extern "C" void kernel_launch(void* const* d_in, const int* in_sizes, int n_in,
                              void* d_out, int out_size)
{
    cudaFuncSetAttribute(coupling_kernel,
                         cudaFuncAttributeMaxDynamicSharedMemorySize,
                         SMEM_FLOATS * 4);
    const float* inp   = (const float*)d_in[0];
    const float* w_in  = (const float*)d_in[1];
    const float* b_in  = (const float*)d_in[2];
    const float* w0a   = (const float*)d_in[3];
    const float* b0a   = (const float*)d_in[4];
    const float* w1a   = (const float*)d_in[5];
    const float* b1a   = (const float*)d_in[6];
    const float* w0b   = (const float*)d_in[7];
    const float* b0b   = (const float*)d_in[8];
    const float* w1b   = (const float*)d_in[9];
    const float* b1b   = (const float*)d_in[10];
    const float* w_out = (const float*)d_in[11];
    const float* b_out = (const float*)d_in[12];
    float* out = (float*)d_out;

    coupling_kernel<<<BTOT / ROWS, NT, SMEM_FLOATS * 4>>>(
        inp, w_in, b_in, w0a, b0a, w1a, b1a, w0b, b0b, w1b, b1b, w_out, b_out, out);
}

// round 5
// speedup vs baseline: 2.4548x; 2.3398x over previous
#include <cuda_runtime.h>
#include <cuda_bf16.h>
#include <cstdint>

#define NTH   256
#define MR    64
#define BTOT  131072
#define GRID  (BTOT / MR)
#define WROWS 2304

// SMEM byte offsets
#define OFF_AH   0        // 65536: h-side operand, bf16 [64][256] hi(0..32767) + lo(32768..)
#define OFF_AT   65536    // 65792: t-side operand (same layout) / ps overlay (64 x 257 fp32)
#define OFF_B    131328   // 49152: two B chunk buffers of 24576 (hi 0..12287, lo 12288..)
#define OFF_SMIN 180480   // 17408: input/output tile fp32 [64][68]
#define SMEM_BYTES 197888

__device__ __align__(16) __nv_bfloat16 g_wsplit[2u * WROWS * 256u];

static __device__ __forceinline__ uint32_t smem_u32(const void* p) {
    uint32_t a;
    asm("{ .reg .u64 t; cvta.to.shared.u64 t, %1; cvt.u32.u64 %0, t; }" : "=r"(a) : "l"(p));
    return a;
}
static __device__ __forceinline__ void ldmx4(uint32_t* r, uint32_t a) {
    asm volatile("ldmatrix.sync.aligned.m8n8.x4.shared.b16 {%0,%1,%2,%3}, [%4];"
                 : "=r"(r[0]), "=r"(r[1]), "=r"(r[2]), "=r"(r[3]) : "r"(a));
}
static __device__ __forceinline__ void mma_bf16(float* c, const uint32_t* a, const uint32_t* b) {
    asm volatile("mma.sync.aligned.m16n8k16.row.col.f32.bf16.bf16.f32 "
                 "{%0,%1,%2,%3}, {%4,%5,%6,%7}, {%8,%9}, {%0,%1,%2,%3};"
                 : "+f"(c[0]), "+f"(c[1]), "+f"(c[2]), "+f"(c[3])
                 : "r"(a[0]), "r"(a[1]), "r"(a[2]), "r"(a[3]), "r"(b[0]), "r"(b[1]));
}
static __device__ __forceinline__ void split2(float x0, float x1, uint32_t& hi, uint32_t& lo) {
    __nv_bfloat162 h2 = __float22bfloat162_rn(make_float2(x0, x1));
    hi = *(uint32_t*)&h2;
    float f0 = __bfloat162float(h2.x), f1 = __bfloat162float(h2.y);
    __nv_bfloat162 l2 = __float22bfloat162_rn(make_float2(x0 - f0, x1 - f1));
    lo = *(uint32_t*)&l2;
}

// ---------------- weight split kernel (fp32 -> bf16 hi/lo planes) ----------------
__global__ void split_weights_kernel(
    const float* __restrict__ w_in, const float* __restrict__ w0a,
    const float* __restrict__ w1a,  const float* __restrict__ w0b,
    const float* __restrict__ w1b,  const float* __restrict__ w_out)
{
    int row = blockIdx.x;
    int c = threadIdx.x;
    float v = 0.f;
    if (row < 256)       { if (c < 32) v = w_in[row * 32 + c]; }
    else if (row < 512)  v = w0a[(row - 256) * 256 + c];
    else if (row < 768)  v = w1a[(row - 512) * 256 + c];
    else if (row < 1024) v = w0b[(row - 768) * 256 + c];
    else if (row < 1280) v = w1b[(row - 1024) * 256 + c];
    else {
        int pr = row - 1280;            // 0..1023, padded w_out: 32 dims x 32 slots
        int dim = pr >> 5, j = pr & 31;
        if (j < 23) v = w_out[(dim * 23 + j) * 256 + c];
    }
    __nv_bfloat16 h = __float2bfloat16(v);
    g_wsplit[row * 256 + c] = h;
    g_wsplit[WROWS * 256 + row * 256 + c] = __float2bfloat16(v - __bfloat162float(h));
}

// ---------------- B chunk staging: 256 rows x 16 k (hi+lo) via cp.async ----------------
static __device__ __forceinline__ void stage(uint32_t bbase, int rowbase, int k0, int tid) {
    #pragma unroll
    for (int i = 0; i < 4; i++) {
        int lin = tid + NTH * i;               // 0..1023
        int half = lin >> 9, idx = lin & 511;
        int row = idx >> 1, piece = idx & 1;
        const __nv_bfloat16* src = g_wsplit + (size_t)half * WROWS * 256
                                 + (size_t)(rowbase + row) * 256 + k0 + piece * 8;
        uint32_t dst = bbase + half * 12288 + row * 48 + piece * 16;
        asm volatile("cp.async.cg.shared.global [%0], [%1], 16;" :: "r"(dst), "l"(src));
    }
}

// ---------------- one K=16 chunk: 12 ldmatrix + 48 mma per warp ----------------
static __device__ __forceinline__ void compute_chunk(
    uint32_t Aop, uint32_t bbuf, float* acc, int wm, int wn, int k0, int lane)
{
    uint32_t ah[2][4], al[2][4];
    #pragma unroll
    for (int mt = 0; mt < 2; mt++) {
        int r = 32 * wm + 16 * mt + (lane & 15);
        int c = (k0 >> 3) + (lane >> 4);
        uint32_t ad = Aop + r * 512 + ((uint32_t)(c ^ ((r & 7) << 2)) << 4);
        ldmx4(ah[mt], ad);
        ldmx4(al[mt], ad + 32768);
    }
    uint32_t bh[4][4], bl[4][4];
    #pragma unroll
    for (int g = 0; g < 4; g++) {
        int r = 64 * wn + 16 * g + (lane & 15);
        uint32_t bd = bbuf + r * 48 + ((lane >> 4) << 4);
        ldmx4(bh[g], bd);
        ldmx4(bl[g], bd + 12288);
    }
    #pragma unroll
    for (int mt = 0; mt < 2; mt++)
        #pragma unroll
        for (int nt = 0; nt < 8; nt++) {
            int g = nt >> 1, o = nt & 1;
            uint32_t b0[2] = { bh[g][o], bh[g][o + 2] };
            uint32_t l0[2] = { bl[g][o], bl[g][o + 2] };
            float* c = acc + (mt * 8 + nt) * 4;
            mma_bf16(c, ah[mt], b0);   // hi*hi
            mma_bf16(c, al[mt], b0);   // lo*hi
            mma_bf16(c, ah[mt], l0);   // hi*lo
        }
}

static __device__ __forceinline__ void run_gemm(
    uint32_t smb, uint32_t Aop, int rowbase, int kch,
    float* acc, int wm, int wn, int lane, int tid)
{
    #pragma unroll
    for (int q = 0; q < 64; q++) acc[q] = 0.f;
    uint32_t b0 = smb + OFF_B, b1 = b0 + 24576;
    stage(b0, rowbase, 0, tid);
    asm volatile("cp.async.commit_group;");
    #pragma unroll 1
    for (int t = 0; t < kch; t++) {
        if (t + 1 < kch) {
            stage((t & 1) ? b0 : b1, rowbase, 16 * (t + 1), tid);
            asm volatile("cp.async.commit_group;");
            asm volatile("cp.async.wait_group 1;");
        } else {
            asm volatile("cp.async.wait_group 0;");
        }
        __syncthreads();
        compute_chunk(Aop, (t & 1) ? b1 : b0, acc, wm, wn, 16 * t, lane);
        __syncthreads();
    }
}

// MODE 0: h=C+b, relu->dst | 1: relu(C+b)->dst | 2: h+=C+b, relu(h)->dst
// MODE 3: h+=C+b, raw h->dst | 4: C->ps (fp32)
template <int MODE>
static __device__ __forceinline__ void epilogue(
    char* sm, const float* acc, float* h, const float* __restrict__ bias,
    uint32_t dstoff, int wm, int wn, int lane)
{
    #pragma unroll
    for (int mt = 0; mt < 2; mt++)
        #pragma unroll
        for (int nt = 0; nt < 8; nt++) {
            const float* a = acc + (mt * 8 + nt) * 4;
            float* hh = h + (mt * 8 + nt) * 4;
            int c0 = 64 * wn + 8 * nt + 2 * (lane & 3);
            float bb0 = (MODE == 4) ? 0.f : __ldg(bias + c0);
            float bb1 = (MODE == 4) ? 0.f : __ldg(bias + c0 + 1);
            #pragma unroll
            for (int hf = 0; hf < 2; hf++) {
                int r = 32 * wm + 16 * mt + (lane >> 2) + 8 * hf;
                float v0 = a[2 * hf] + bb0, v1 = a[2 * hf + 1] + bb1;
                if (MODE == 2 || MODE == 3) { v0 += hh[2 * hf]; v1 += hh[2 * hf + 1]; }
                if (MODE == 0 || MODE == 2 || MODE == 3) { hh[2 * hf] = v0; hh[2 * hf + 1] = v1; }
                if (MODE == 4) {
                    float* ps = (float*)(sm + OFF_AT);
                    ps[r * 257 + c0]     = v0;
                    ps[r * 257 + c0 + 1] = v1;
                } else {
                    float w0 = v0, w1 = v1;
                    if (MODE != 3) { w0 = fmaxf(w0, 0.f); w1 = fmaxf(w1, 0.f); }
                    uint32_t hi, lo;
                    split2(w0, w1, hi, lo);
                    int u = 8 * wn + nt;
                    uint32_t off = dstoff + r * 512
                                 + ((uint32_t)(u ^ ((r & 7) << 2)) << 4) + 4 * (lane & 3);
                    *(uint32_t*)(sm + off)         = hi;
                    *(uint32_t*)(sm + off + 32768) = lo;
                }
            }
        }
}

__global__ void __launch_bounds__(NTH, 1)
coupling_mma_kernel(const float* __restrict__ inp,
                    const float* __restrict__ b_in,
                    const float* __restrict__ b0a, const float* __restrict__ b1a,
                    const float* __restrict__ b0b, const float* __restrict__ b1b,
                    const float* __restrict__ b_out,
                    float* __restrict__ out)
{
    extern __shared__ char sm[];
    const int tid = threadIdx.x, lane = tid & 31, wrp = tid >> 5;
    const int wm = wrp >> 2, wn = wrp & 3;        // 2 x 4 warp grid
    const int row0 = blockIdx.x * MR;
    const uint32_t smb = smem_u32(sm);
    float* smin = (float*)(sm + OFF_SMIN);

    // ---- load input tile 64 x 64 (stride 68) ----
    #pragma unroll
    for (int i = 0; i < 16; i++) {
        int idx = tid + NTH * i;
        int r = idx >> 6, c = idx & 63;
        smin[r * 68 + c] = inp[(size_t)(row0 + r) * 64 + c];
    }
    __syncthreads();

    // ---- ident (odd cols) -> A_H as bf16 hi/lo, k = 0..31 ----
    {
        int r = tid >> 2, s = tid & 3;
        #pragma unroll
        for (int kk = 0; kk < 8; kk += 2) {
            int k = 8 * s + kk;
            float v0 = smin[r * 68 + 2 * k + 1];
            float v1 = smin[r * 68 + 2 * k + 3];
            uint32_t hi, lo;
            split2(v0, v1, hi, lo);
            uint32_t off = OFF_AH + r * 512
                         + ((uint32_t)(s ^ ((r & 7) << 2)) << 4) + 2 * kk;
            *(uint32_t*)(sm + off)         = hi;
            *(uint32_t*)(sm + off + 32768) = lo;
        }
    }
    // visibility guaranteed by the __syncthreads inside run_gemm before first compute

    float acc[64], h[64];
    const uint32_t AH = smb + OFF_AH, AT = smb + OFF_AT;

    run_gemm(smb, AH, 0,    2,  acc, wm, wn, lane, tid);   // w_in  (K=32)
    epilogue<0>(sm, acc, h, b_in, OFF_AH, wm, wn, lane);
    run_gemm(smb, AH, 256,  16, acc, wm, wn, lane, tid);   // w0a
    epilogue<1>(sm, acc, h, b0a, OFF_AT, wm, wn, lane);
    run_gemm(smb, AT, 512,  16, acc, wm, wn, lane, tid);   // w1a
    epilogue<2>(sm, acc, h, b1a, OFF_AH, wm, wn, lane);
    run_gemm(smb, AH, 768,  16, acc, wm, wn, lane, tid);   // w0b
    epilogue<1>(sm, acc, h, b0b, OFF_AT, wm, wn, lane);
    run_gemm(smb, AT, 1024, 16, acc, wm, wn, lane, tid);   // w1b -> raw h
    epilogue<3>(sm, acc, h, b1b, OFF_AH, wm, wn, lane);

    // ---- w_out: 4 passes x 256 padded cols (8 dims of 32 slots each) ----
    float lad = 0.f;
    float* ps = (float*)(sm + OFF_AT);
    #pragma unroll 1
    for (int p = 0; p < 4; p++) {
        run_gemm(smb, AH, 1280 + 256 * p, 16, acc, wm, wn, lane, tid);
        epilogue<4>(sm, acc, h, nullptr, 0, wm, wn, lane);
        __syncthreads();
        int r = tid >> 2, s = tid & 3;
        #pragma unroll 1
        for (int dd = 0; dd < 2; dd++) {
            int dl = s + 4 * dd;
            int gd = 8 * p + dl;
            const float* qp = ps + r * 257 + dl * 32;
            float pp[23];
            #pragma unroll
            for (int j = 0; j < 23; j++) pp[j] = qp[j] + __ldg(b_out + gd * 23 + j);
            float knw[9], knh[9], dv[9];
            {
                float e[8], mx = -1e30f;
                #pragma unroll
                for (int j = 0; j < 8; j++) { e[j] = pp[j] * 0.0625f; mx = fmaxf(mx, e[j]); }
                float se = 0.f;
                #pragma unroll
                for (int j = 0; j < 8; j++) { e[j] = expf(e[j] - mx); se += e[j]; }
                float inv = 1.f / se, cum = 0.f;
                knw[0] = -3.f;
                #pragma unroll
                for (int j = 0; j < 8; j++) { cum += 0.001f + 0.992f * e[j] * inv; knw[j + 1] = 6.f * cum - 3.f; }
                knw[8] = 3.f;
            }
            {
                float e[8], mx = -1e30f;
                #pragma unroll
                for (int j = 0; j < 8; j++) { e[j] = pp[8 + j] * 0.0625f; mx = fmaxf(mx, e[j]); }
                float se = 0.f;
                #pragma unroll
                for (int j = 0; j < 8; j++) { e[j] = expf(e[j] - mx); se += e[j]; }
                float inv = 1.f / se, cum = 0.f;
                knh[0] = -3.f;
                #pragma unroll
                for (int j = 0; j < 8; j++) { cum += 0.001f + 0.992f * e[j] * inv; knh[j + 1] = 6.f * cum - 3.f; }
                knh[8] = 3.f;
            }
            dv[0] = 1.f; dv[8] = 1.f;
            #pragma unroll
            for (int j = 1; j < 8; j++) {
                float t = pp[15 + j];
                dv[j] = 0.001f + fmaxf(t, 0.f) + log1pf(expf(-fabsf(t)));
            }
            float x  = smin[r * 68 + 2 * gd];
            float xc = fminf(fmaxf(x, -3.f), 3.f);
            int idx = -1;
            #pragma unroll
            for (int j = 0; j < 9; j++) idx += (xc >= knw[j]) ? 1 : 0;
            idx = min(max(idx, 0), 7);
            float kw0 = knw[idx], kw1 = knw[idx + 1];
            float kh0 = knh[idx], kh1 = knh[idx + 1];
            float wdt = kw1 - kw0, hgt = kh1 - kh0;
            float delta = hgt / wdt;
            float d0v = dv[idx], d1v = dv[idx + 1];
            float th  = (xc - kw0) / wdt;
            float tom = th * (1.f - th);
            float num = hgt * (delta * th * th + d0v * tom);
            float den = delta + (d0v + d1v - 2.f * delta) * tom;
            float y   = kh0 + num / den;
            float omt = 1.f - th;
            float dnum = delta * delta * (d1v * th * th + 2.f * delta * tom + d0v * omt * omt);
            float ld   = logf(dnum) - 2.f * logf(den);
            bool inside = (x >= -3.f) && (x <= 3.f);
            if (!inside) { y = x; ld = 0.f; }
            smin[r * 68 + 2 * gd] = y;
            lad += ld;
        }
        __syncthreads();    // ps fully consumed before next pass overwrites it
    }

    lad += __shfl_xor_sync(0xffffffffu, lad, 1);
    lad += __shfl_xor_sync(0xffffffffu, lad, 2);

    __syncthreads();
    #pragma unroll
    for (int i = 0; i < 16; i++) {
        int idx = tid + NTH * i;
        int r = idx >> 6, c = idx & 63;
        out[(size_t)(row0 + r) * 64 + c] = smin[r * 68 + c];
    }
    if ((tid & 3) == 0) out[(size_t)BTOT * 64 + row0 + (tid >> 2)] = lad;
}

extern "C" void kernel_launch(void* const* d_in, const int* in_sizes, int n_in,
                              void* d_out, int out_size)
{
    cudaFuncSetAttribute(coupling_mma_kernel,
                         cudaFuncAttributeMaxDynamicSharedMemorySize, SMEM_BYTES);
    const float* inp   = (const float*)d_in[0];
    const float* w_in  = (const float*)d_in[1];
    const float* b_in  = (const float*)d_in[2];
    const float* w0a   = (const float*)d_in[3];
    const float* b0a   = (const float*)d_in[4];
    const float* w1a   = (const float*)d_in[5];
    const float* b1a   = (const float*)d_in[6];
    const float* w0b   = (const float*)d_in[7];
    const float* b0b   = (const float*)d_in[8];
    const float* w1b   = (const float*)d_in[9];
    const float* b1b   = (const float*)d_in[10];
    const float* w_out = (const float*)d_in[11];
    const float* b_out = (const float*)d_in[12];
    float* out = (float*)d_out;

    split_weights_kernel<<<WROWS, 256>>>(w_in, w0a, w1a, w0b, w1b, w_out);
    coupling_mma_kernel<<<GRID, NTH, SMEM_BYTES>>>(
        inp, b_in, b0a, b1a, b0b, b1b, b_out, out);
}